// round 2
// baseline (speedup 1.0000x reference)
#include <cuda_runtime.h>
#include <math.h>

// ---------------- problem constants ----------------
#define Bsz 2
#define Nn  2048
#define Dd  128
#define Hh  4
#define Ff  64
#define HF  256
#define FC1n 1024
#define FC2n 256

// output layout (f32):
// [0,12288)      gat_features [B, 3N]
// [12288,12800)  fc_features  [B, 256]
// [12800,12804)  logits       [B, 2]
// [12804, ...)   attention_map [B, N, N, 1]
#define OUT_GAT 0
#define OUT_FC  12288
#define OUT_LOG 12800
#define OUT_MAP 12804

// ---------------- scratch (static device globals; no runtime alloc) ----------------
__device__ float g_wcat1[Dd * HF];            // 128x256
__device__ float g_wcat2[HF * HF];            // 256x256
__device__ float g_hproj[Bsz * Nn * HF];      // projections h (per layer, reused)
__device__ float g_x1[Bsz * Nn * HF];         // layer-1 output
__device__ float g_x2[Bsz * Nn * HF];         // layer-2 output
__device__ float g_es[Bsz * Hh * Nn];
__device__ float g_ed[Bsz * Hh * Nn];
__device__ float g_att[(long)Bsz * Hh * Nn * Nn];  // 134 MB
__device__ float g_fc1[Bsz * FC1n];
__device__ float g_y1[Bsz * FC1n];
__device__ float g_fc2[Bsz * FC2n];
__device__ float g_part[8 * Bsz * FC1n];      // split-K partials

// ---------------- f32x2 helpers ----------------
__device__ __forceinline__ unsigned long long pack2(float x, float y) {
    unsigned long long r;
    asm("mov.b64 %0, {%1, %2};" : "=l"(r) : "r"(__float_as_uint(x)), "r"(__float_as_uint(y)));
    return r;
}
__device__ __forceinline__ unsigned long long rep2(float x) {
    unsigned long long r;
    unsigned u = __float_as_uint(x);
    asm("mov.b64 %0, {%1, %1};" : "=l"(r) : "r"(u));
    return r;
}
__device__ __forceinline__ void fma2(unsigned long long &d, unsigned long long a, unsigned long long b) {
    asm("fma.rn.f32x2 %0, %1, %2, %0;" : "+l"(d) : "l"(a), "l"(b));
}
__device__ __forceinline__ float2 unpk2(unsigned long long v) {
    float2 f;
    f.x = __uint_as_float((unsigned)v);
    f.y = __uint_as_float((unsigned)(v >> 32));
    return f;
}

// ---------------- kernels ----------------

// repack W1 [H,D,F] -> wcat1[d][h*F+f], W2 [H,HF,F] -> wcat2[k][h*F+f]
__global__ void repack_k(const float* __restrict__ W1, const float* __restrict__ W2) {
    int t = blockIdx.x * blockDim.x + threadIdx.x;
    if (t < Hh * Dd * Ff) {
        int h = t / (Dd * Ff); int r = t % (Dd * Ff); int d = r / Ff; int f = r % Ff;
        g_wcat1[d * HF + h * Ff + f] = W1[t];
    }
    if (t < Hh * HF * Ff) {
        int h = t / (HF * Ff); int r = t % (HF * Ff); int k = r / Ff; int f = r % Ff;
        g_wcat2[k * HF + h * Ff + f] = W2[t];
    }
}

// GEMM: C[M x Nc] = A[M x K] * B[K x Nc]. Tile 128x64x16, 256 thr, micro 8x4 via f32x2.
// mode 0: proj1  x[4096x128]   @ wcat1[128x256] -> hproj   grid(32,4,1)
// mode 1: proj2  x1[4096x256]  @ wcat2[256x256] -> hproj   grid(32,4,1)
// mode 2: att@h  att[bh][2048x2048] @ hproj[.,h] -> x1     grid(16,1,8), relu
// mode 3: same -> x2                                        grid(16,1,8), relu
__global__ void __launch_bounds__(256) gemm_k(const float* __restrict__ xin, int mode) {
    const long NN = (long)Nn * Nn;
    const float *A, *B;
    float *C;
    int K, lda, relu = 0;
    if (mode == 0)      { A = xin;  B = g_wcat1; C = g_hproj; K = Dd; lda = Dd; }
    else if (mode == 1) { A = g_x1; B = g_wcat2; C = g_hproj; K = HF; lda = HF; }
    else {
        int z = blockIdx.z, zb = z >> 2, zh = z & 3;
        A = g_att + (long)z * NN;
        B = g_hproj + (long)zb * Nn * HF + zh * Ff;
        C = (mode == 2 ? g_x1 : g_x2) + (long)zb * Nn * HF + zh * Ff;
        K = Nn; lda = Nn; relu = 1;
    }
    const int ldb = HF, ldc = HF;

    __shared__ float As[16][128];
    __shared__ float Bs[16][64];

    int tid = threadIdx.x;
    int m0 = blockIdx.x * 128, n0 = blockIdx.y * 64;
    int tx = tid & 15, ty = tid >> 4;
    int a_r = tid >> 2, a_k = (tid & 3) << 2;
    int b_k = tid >> 4, b_n = (tid & 15) << 2;

    const float* Ap0 = A + (long)(m0 + a_r) * lda + a_k;
    const float* Ap1 = Ap0 + (long)64 * lda;
    const float* Bp  = B + (long)b_k * ldb + n0 + b_n;

    unsigned long long acc[4][4];
#pragma unroll
    for (int i = 0; i < 4; i++)
#pragma unroll
        for (int j = 0; j < 4; j++) acc[i][j] = 0ULL;

    float4 av0 = *(const float4*)Ap0;
    float4 av1 = *(const float4*)Ap1;
    float4 bv  = *(const float4*)Bp;

    for (int k0 = 0; k0 < K; k0 += 16) {
        __syncthreads();
        As[a_k + 0][a_r] = av0.x; As[a_k + 1][a_r] = av0.y;
        As[a_k + 2][a_r] = av0.z; As[a_k + 3][a_r] = av0.w;
        As[a_k + 0][a_r + 64] = av1.x; As[a_k + 1][a_r + 64] = av1.y;
        As[a_k + 2][a_r + 64] = av1.z; As[a_k + 3][a_r + 64] = av1.w;
        *(float4*)&Bs[b_k][b_n] = bv;
        __syncthreads();
        if (k0 + 16 < K) {
            av0 = *(const float4*)(Ap0 + k0 + 16);
            av1 = *(const float4*)(Ap1 + k0 + 16);
            bv  = *(const float4*)(Bp + (long)(k0 + 16) * ldb);
        }
#pragma unroll
        for (int kk = 0; kk < 16; kk++) {
            float4 aA = *(const float4*)&As[kk][ty * 8];
            float4 aB = *(const float4*)&As[kk][ty * 8 + 4];
            float4 b4 = *(const float4*)&Bs[kk][tx * 4];
            unsigned long long au[4], bu[4];
            au[0] = pack2(aA.x, aA.y); au[1] = pack2(aA.z, aA.w);
            au[2] = pack2(aB.x, aB.y); au[3] = pack2(aB.z, aB.w);
            bu[0] = rep2(b4.x); bu[1] = rep2(b4.y);
            bu[2] = rep2(b4.z); bu[3] = rep2(b4.w);
#pragma unroll
            for (int ip = 0; ip < 4; ip++)
#pragma unroll
                for (int j = 0; j < 4; j++) fma2(acc[ip][j], au[ip], bu[j]);
        }
    }

#pragma unroll
    for (int ip = 0; ip < 4; ip++) {
        float2 c0 = unpk2(acc[ip][0]), c1 = unpk2(acc[ip][1]);
        float2 c2 = unpk2(acc[ip][2]), c3 = unpk2(acc[ip][3]);
        float4 lo = make_float4(c0.x, c1.x, c2.x, c3.x);
        float4 hi = make_float4(c0.y, c1.y, c2.y, c3.y);
        if (relu) {
            lo.x = fmaxf(lo.x, 0.f); lo.y = fmaxf(lo.y, 0.f); lo.z = fmaxf(lo.z, 0.f); lo.w = fmaxf(lo.w, 0.f);
            hi.x = fmaxf(hi.x, 0.f); hi.y = fmaxf(hi.y, 0.f); hi.z = fmaxf(hi.z, 0.f); hi.w = fmaxf(hi.w, 0.f);
        }
        int r0 = m0 + ty * 8 + 2 * ip;
        *(float4*)&C[(long)r0 * ldc + n0 + tx * 4] = lo;
        *(float4*)&C[(long)(r0 + 1) * ldc + n0 + tx * 4] = hi;
    }
}

// es/ed: one warp per (b,h,n) row; dot over F=64 with a_src/a_dst
__global__ void esed_k(const float* __restrict__ asrc, const float* __restrict__ adst)
{
    int warp = (blockIdx.x * blockDim.x + threadIdx.x) >> 5;   // (b*H+h)*N+n
    int lane = threadIdx.x & 31;
    int b = warp >> 13;
    int rem = warp & 8191;
    int h = rem >> 11;
    int n = rem & 2047;
    const float* hr = g_hproj + ((long)(b * Nn + n) * HF + h * Ff);
    float v0 = hr[lane], v1 = hr[lane + 32];
    float s = v0 * asrc[h * Ff + lane] + v1 * asrc[h * Ff + lane + 32];
    float d = v0 * adst[h * Ff + lane] + v1 * adst[h * Ff + lane + 32];
#pragma unroll
    for (int o = 16; o; o >>= 1) {
        s += __shfl_xor_sync(0xffffffffu, s, o);
        d += __shfl_xor_sync(0xffffffffu, d, o);
    }
    if (!lane) { g_es[warp] = s; g_ed[warp] = d; }
}

// Row softmax for all heads of one (b,i); no max pass (scores bounded, masked->exact 0).
// Writes g_att and attention_map (0.125*w per head; layer 1 adds into map).
__global__ void __launch_bounds__(256) softmax_att_k(const int* __restrict__ adj,
                                                     int layer, float* __restrict__ omap)
{
    __shared__ float red[8];
    int bi = blockIdx.x;
    int b = bi >> 11, i = bi & 2047;
    int tid = threadIdx.x, lane = tid & 31, wid = tid >> 5;

    const int* adjrow = adj + (long)i * Nn;
    float msk[8], amap[8];
#pragma unroll
    for (int k = 0; k < 8; k++) {
        msk[k] = (adjrow[tid + 256 * k] > 0) ? 1.f : 0.f;
        amap[k] = 0.f;
    }

    for (int hh = 0; hh < Hh; hh++) {
        int ro = ((b << 2) + hh) << 11;
        float esi = g_es[ro + i];
        const float* edp = g_ed + ro;

        float p[8];
        float lsum = 0.f;
#pragma unroll
        for (int k = 0; k < 8; k++) {
            float s = esi + edp[tid + 256 * k];
            float e = fmaxf(s, 0.2f * s);          // leaky_relu(s, 0.2)
            float pe = __expf(e) * msk[k];
            p[k] = pe;
            lsum += pe;
        }
#pragma unroll
        for (int o = 16; o; o >>= 1) lsum += __shfl_xor_sync(0xffffffffu, lsum, o);
        if (!lane) red[wid] = lsum;
        __syncthreads();
        float inv = 1.f / (red[0] + red[1] + red[2] + red[3] +
                           red[4] + red[5] + red[6] + red[7]);
        __syncthreads();

        float* arow = g_att + ((long)(ro + i) << 11);
#pragma unroll
        for (int k = 0; k < 8; k++) {
            float w = p[k] * inv;
            arow[tid + 256 * k] = w;
            amap[k] += 0.125f * w;
        }
    }

    float* mrow = omap + ((long)bi << 11);
    if (layer == 0) {
#pragma unroll
        for (int k = 0; k < 8; k++) mrow[tid + 256 * k] = amap[k];
    } else {
#pragma unroll
        for (int k = 0; k < 8; k++) mrow[tid + 256 * k] += amap[k];
    }
}

// pooling / mean: one warp per (b,n) row.
// mode 0: x param (rowlen 128, mean).  mode 1: g_x1 dot pool1_W.  mode 2: g_x2 dot pool2_W.
__global__ void pool_k(const float* __restrict__ xparam,
                       const float* __restrict__ w, const float* __restrict__ wb,
                       float* __restrict__ out, int mode)
{
    int warp = (blockIdx.x * 256 + threadIdx.x) >> 5;   // 0..4095
    int lane = threadIdx.x & 31;
    const float* rows; int rowlen, off; float scale;
    if (mode == 0)      { rows = xparam; rowlen = Dd; off = 0;      scale = 1.f / 128.f; }
    else if (mode == 1) { rows = g_x1;   rowlen = HF; off = Nn;     scale = 1.f; }
    else                { rows = g_x2;   rowlen = HF; off = 2 * Nn; scale = 1.f; }
    const float* rp = rows + (long)warp * rowlen;
    float acc = 0.f;
    if (mode == 0) { for (int c = lane; c < rowlen; c += 32) acc += rp[c]; }
    else           { for (int c = lane; c < rowlen; c += 32) acc += rp[c] * w[c]; }
#pragma unroll
    for (int o = 16; o; o >>= 1) acc += __shfl_xor_sync(0xffffffffu, acc, o);
    if (!lane) {
        int b = warp >> 11, n = warp & 2047;
        out[(long)b * (3 * Nn) + off + n] = acc * scale + (mode == 0 ? 0.f : wb[0]);
    }
}

// split-K GEMV partials: grid (OC/64, 8); both batch rows per thread.
// use_y1: input is g_y1 (else in_param).
__global__ void __launch_bounds__(256) fc_part_k(const float* __restrict__ in_param,
                                                 const float* __restrict__ W,
                                                 int use_y1, int IC, int OC)
{
    __shared__ float red0[256], red1[256];
    const float* in = use_y1 ? (const float*)g_y1 : in_param;
    int tid = threadIdx.x;
    int cl = tid & 63, ks = tid >> 6;
    int c = blockIdx.x * 64 + cl;
    int kchunk = IC >> 5;
    int k0 = (blockIdx.y * 4 + ks) * kchunk;
    const float* in0 = in;
    const float* in1 = in + IC;
    float a0 = 0.f, a1 = 0.f;
#pragma unroll 4
    for (int k = k0; k < k0 + kchunk; k++) {
        float w = W[(long)k * OC + c];
        a0 += in0[k] * w;
        a1 += in1[k] * w;
    }
    red0[tid] = a0; red1[tid] = a1;
    __syncthreads();
    if (ks == 0) {
        a0 = red0[tid] + red0[tid + 64] + red0[tid + 128] + red0[tid + 192];
        a1 = red1[tid] + red1[tid + 64] + red1[tid + 128] + red1[tid + 192];
        long base = (long)blockIdx.y * (2 * OC);
        g_part[base + c] = a0;
        g_part[base + OC + c] = a1;
    }
}

// reduce 8 partial slices + bias.  mode 0 -> g_fc1, mode 1 -> g_fc2.
__global__ void fc_reduce_k(const float* __restrict__ bias, int mode, int OC, int tot)
{
    int t = blockIdx.x * 256 + threadIdx.x;
    if (t >= tot) return;
    float s = bias[t % OC];
#pragma unroll
    for (int p = 0; p < 8; p++) s += g_part[(long)p * tot + t];
    if (mode == 0) g_fc1[t] = s; else g_fc2[t] = s;
}

// LayerNorm + ReLU, one CTA per batch row.
// mode 0: g_fc1 -> g_y1 (C=1024).  mode 1: g_fc2 -> out_param (C=256).
__global__ void ln_relu_k(int mode, float* __restrict__ out_param,
                          const float* __restrict__ g, const float* __restrict__ be)
{
    __shared__ float r1[8], r2[8];
    int C = (mode == 0) ? FC1n : FC2n;
    const float* in = (mode == 0) ? (const float*)g_fc1 : (const float*)g_fc2;
    float* outp = (mode == 0) ? (float*)g_y1 : out_param;
    int b = blockIdx.x, tid = threadIdx.x, lane = tid & 31, wid = tid >> 5;
    const float* row = in + (long)b * C;
    float s = 0.f, ss = 0.f;
    for (int c = tid; c < C; c += 256) { float v = row[c]; s += v; ss += v * v; }
#pragma unroll
    for (int o = 16; o; o >>= 1) {
        s  += __shfl_xor_sync(0xffffffffu, s, o);
        ss += __shfl_xor_sync(0xffffffffu, ss, o);
    }
    if (!lane) { r1[wid] = s; r2[wid] = ss; }
    __syncthreads();
    s = 0.f; ss = 0.f;
#pragma unroll
    for (int w = 0; w < 8; w++) { s += r1[w]; ss += r2[w]; }
    float m = s / C;
    float var = ss / C - m * m;
    float r = rsqrtf(var + 1e-5f);
    for (int c = tid; c < C; c += 256) {
        float v = row[c];
        outp[(long)b * C + c] = fmaxf((v - m) * r * g[c] + be[c], 0.f);
    }
}

// classifier: logits[b,l] = dot(feat[b], cls_W[:,l]) + cls_b[l]
__global__ void cls_k(const float* __restrict__ feat, const float* __restrict__ W,
                      const float* __restrict__ wb, float* __restrict__ out)
{
    int tid = threadIdx.x;
    if (tid >= 128) return;
    int lane = tid & 31, w = tid >> 5;
    int b = w >> 1, l = w & 1;
    float acc = 0.f;
    for (int k = lane; k < FC2n; k += 32) acc += feat[b * FC2n + k] * W[k * 2 + l];
#pragma unroll
    for (int o = 16; o; o >>= 1) acc += __shfl_xor_sync(0xffffffffu, acc, o);
    if (!lane) out[b * 2 + l] = acc + wb[l];
}

// ---------------- host launcher (launches only; nothing else) ----------------
extern "C" void kernel_launch(void* const* d_in, const int* in_sizes, int n_in,
                              void* d_out, int out_size)
{
    const float* x        = (const float*)d_in[0];
    const int*   adj      = (const int*)  d_in[1];
    const float* a1_src   = (const float*)d_in[4];
    const float* a1_dst   = (const float*)d_in[5];
    const float* pool1_W  = (const float*)d_in[6];
    const float* pool1_b  = (const float*)d_in[7];
    const float* a2_src   = (const float*)d_in[9];
    const float* a2_dst   = (const float*)d_in[10];
    const float* pool2_W  = (const float*)d_in[11];
    const float* pool2_b  = (const float*)d_in[12];
    const float* fc1_W    = (const float*)d_in[13];
    const float* fc1_b    = (const float*)d_in[14];
    const float* ln1_g    = (const float*)d_in[15];
    const float* ln1_b    = (const float*)d_in[16];
    const float* fc2_W    = (const float*)d_in[17];
    const float* fc2_b    = (const float*)d_in[18];
    const float* ln2_g    = (const float*)d_in[19];
    const float* ln2_b    = (const float*)d_in[20];
    const float* cls_W    = (const float*)d_in[21];
    const float* cls_b    = (const float*)d_in[22];

    float* out = (float*)d_out;

    // 1) repack weights
    repack_k<<<256, 256>>>((const float*)d_in[3], (const float*)d_in[8]);

    // 2) layer-1 projection
    gemm_k<<<dim3(32, 4, 1), 256>>>(x, 0);

    // 3) es/ed layer 1
    esed_k<<<2048, 256>>>(a1_src, a1_dst);

    // 4) softmax + att + attention map (layer 1)
    softmax_att_k<<<4096, 256>>>(adj, 0, out + OUT_MAP);

    // 5) att @ h -> x1 (relu)
    gemm_k<<<dim3(16, 1, 8), 256>>>(x, 2);

    // 6) x0 mean pool + p1 pool
    pool_k<<<512, 256>>>(x, pool1_W, pool1_b, out + OUT_GAT, 0);
    pool_k<<<512, 256>>>(x, pool1_W, pool1_b, out + OUT_GAT, 1);

    // 7) layer-2 projection
    gemm_k<<<dim3(32, 4, 1), 256>>>(x, 1);

    // 8) es/ed layer 2
    esed_k<<<2048, 256>>>(a2_src, a2_dst);

    // 9) softmax layer 2 (adds into attention map)
    softmax_att_k<<<4096, 256>>>(adj, 1, out + OUT_MAP);

    // 10) att @ h -> x2 (relu)
    gemm_k<<<dim3(16, 1, 8), 256>>>(x, 3);

    // 11) p2 pool
    pool_k<<<512, 256>>>(x, pool2_W, pool2_b, out + OUT_GAT, 2);

    // 12) MLP head
    fc_part_k<<<dim3(16, 8), 256>>>(out + OUT_GAT, fc1_W, 0, 3 * Nn, FC1n);
    fc_reduce_k<<<8, 256>>>(fc1_b, 0, FC1n, Bsz * FC1n);
    ln_relu_k<<<2, 256>>>(0, out, ln1_g, ln1_b);

    fc_part_k<<<dim3(4, 8), 256>>>(out, fc2_W, 1, FC1n, FC2n);
    fc_reduce_k<<<2, 256>>>(fc2_b, 1, FC2n, Bsz * FC2n);
    ln_relu_k<<<2, 256>>>(1, out + OUT_FC, ln2_g, ln2_b);

    cls_k<<<1, 128>>>(out + OUT_FC, cls_W, cls_b, out + OUT_LOG);
}

// round 4
// speedup vs baseline: 1.6177x; 1.6177x over previous
#include <cuda_runtime.h>
#include <cuda_bf16.h>
#include <mma.h>
#include <math.h>
#include <stdint.h>

using namespace nvcuda;

// ---------------- problem constants ----------------
#define Bsz 2
#define Nn  2048
#define Dd  128
#define Hh  4
#define Ff  64
#define HF  256
#define FC1n 1024
#define FC2n 256

// output layout (f32)
#define OUT_GAT 0
#define OUT_FC  12288
#define OUT_LOG 12800
#define OUT_MAP 12804

// ---------------- scratch ----------------
__device__ float g_wcat1[Dd * HF];
__device__ float g_wcat2[HF * HF];
__device__ float g_hproj[Bsz * Nn * HF];
__device__ float g_x1[Bsz * Nn * HF];
__device__ float g_x2[Bsz * Nn * HF];
__device__ float g_es[Bsz * Hh * Nn];
__device__ float g_ed[Bsz * Hh * Nn];
__device__ __nv_bfloat16 g_atth[(long)Bsz * Hh * Nn * Nn];   // 67 MB
__device__ __nv_bfloat16 g_attl[(long)Bsz * Hh * Nn * Nn];   // 67 MB
__device__ __nv_bfloat16 g_hTh[Bsz * HF * Nn];               // h^T hi
__device__ __nv_bfloat16 g_hTl[Bsz * HF * Nn];               // h^T lo
__device__ float g_fc1[Bsz * FC1n];
__device__ float g_y1[Bsz * FC1n];
__device__ float g_fc2[Bsz * FC2n];
__device__ float g_part[8 * Bsz * FC1n];

// ---------------- f32x2 helpers (SIMT proj GEMM) ----------------
__device__ __forceinline__ unsigned long long pack2(float x, float y) {
    unsigned long long r;
    asm("mov.b64 %0, {%1, %2};" : "=l"(r) : "r"(__float_as_uint(x)), "r"(__float_as_uint(y)));
    return r;
}
__device__ __forceinline__ unsigned long long rep2(float x) {
    unsigned long long r; unsigned u = __float_as_uint(x);
    asm("mov.b64 %0, {%1, %1};" : "=l"(r) : "r"(u));
    return r;
}
__device__ __forceinline__ void fma2(unsigned long long &d, unsigned long long a, unsigned long long b) {
    asm("fma.rn.f32x2 %0, %1, %2, %0;" : "+l"(d) : "l"(a), "l"(b));
}
__device__ __forceinline__ float2 unpk2(unsigned long long v) {
    float2 f; f.x = __uint_as_float((unsigned)v); f.y = __uint_as_float((unsigned)(v >> 32));
    return f;
}

// ---------------- cp.async helpers ----------------
__device__ __forceinline__ uint32_t smem_u32(const void* p) {
    uint32_t a;
    asm("{ .reg .u64 t; cvta.to.shared.u64 t, %1; cvt.u32.u64 %0, t; }" : "=r"(a) : "l"(p));
    return a;
}
#define CP16(saddr, gptr) asm volatile("cp.async.cg.shared.global [%0], [%1], 16;" :: "r"(saddr), "l"(gptr) : "memory")
#define CP_COMMIT() asm volatile("cp.async.commit_group;" ::: "memory")
#define CP_WAIT1()  asm volatile("cp.async.wait_group 1;" ::: "memory")
#define CP_WAIT0()  asm volatile("cp.async.wait_group 0;" ::: "memory")

// ---------------- repack ----------------
__global__ void repack_k(const float* __restrict__ W1, const float* __restrict__ W2) {
    int t = blockIdx.x * blockDim.x + threadIdx.x;
    if (t < Hh * Dd * Ff) {
        int h = t / (Dd * Ff); int r = t % (Dd * Ff); int d = r / Ff; int f = r % Ff;
        g_wcat1[d * HF + h * Ff + f] = W1[t];
    }
    if (t < Hh * HF * Ff) {
        int h = t / (HF * Ff); int r = t % (HF * Ff); int k = r / Ff; int f = r % Ff;
        g_wcat2[k * HF + h * Ff + f] = W2[t];
    }
}

// ---------------- SIMT projection GEMM (modes 0/1) ----------------
__global__ void __launch_bounds__(256) gemm_k(const float* __restrict__ xin, int mode) {
    const float *A, *B; float *C; int K, lda;
    if (mode == 0) { A = xin;  B = g_wcat1; C = g_hproj; K = Dd; lda = Dd; }
    else           { A = g_x1; B = g_wcat2; C = g_hproj; K = HF; lda = HF; }
    const int ldb = HF, ldc = HF;

    __shared__ float As[16][128];
    __shared__ float Bs[16][64];

    int tid = threadIdx.x;
    int m0 = blockIdx.x * 128, n0 = blockIdx.y * 64;
    int tx = tid & 15, ty = tid >> 4;
    int a_r = tid >> 2, a_k = (tid & 3) << 2;
    int b_k = tid >> 4, b_n = (tid & 15) << 2;

    const float* Ap0 = A + (long)(m0 + a_r) * lda + a_k;
    const float* Ap1 = Ap0 + (long)64 * lda;
    const float* Bp  = B + (long)b_k * ldb + n0 + b_n;

    unsigned long long acc[4][4];
#pragma unroll
    for (int i = 0; i < 4; i++)
#pragma unroll
        for (int j = 0; j < 4; j++) acc[i][j] = 0ULL;

    float4 av0 = *(const float4*)Ap0;
    float4 av1 = *(const float4*)Ap1;
    float4 bv  = *(const float4*)Bp;

    for (int k0 = 0; k0 < K; k0 += 16) {
        __syncthreads();
        As[a_k + 0][a_r] = av0.x; As[a_k + 1][a_r] = av0.y;
        As[a_k + 2][a_r] = av0.z; As[a_k + 3][a_r] = av0.w;
        As[a_k + 0][a_r + 64] = av1.x; As[a_k + 1][a_r + 64] = av1.y;
        As[a_k + 2][a_r + 64] = av1.z; As[a_k + 3][a_r + 64] = av1.w;
        *(float4*)&Bs[b_k][b_n] = bv;
        __syncthreads();
        if (k0 + 16 < K) {
            av0 = *(const float4*)(Ap0 + k0 + 16);
            av1 = *(const float4*)(Ap1 + k0 + 16);
            bv  = *(const float4*)(Bp + (long)(k0 + 16) * ldb);
        }
#pragma unroll
        for (int kk = 0; kk < 16; kk++) {
            float4 aA = *(const float4*)&As[kk][ty * 8];
            float4 aB = *(const float4*)&As[kk][ty * 8 + 4];
            float4 b4 = *(const float4*)&Bs[kk][tx * 4];
            unsigned long long au[4], bu[4];
            au[0] = pack2(aA.x, aA.y); au[1] = pack2(aA.z, aA.w);
            au[2] = pack2(aB.x, aB.y); au[3] = pack2(aB.z, aB.w);
            bu[0] = rep2(b4.x); bu[1] = rep2(b4.y); bu[2] = rep2(b4.z); bu[3] = rep2(b4.w);
#pragma unroll
            for (int ip = 0; ip < 4; ip++)
#pragma unroll
                for (int j = 0; j < 4; j++) fma2(acc[ip][j], au[ip], bu[j]);
        }
    }
#pragma unroll
    for (int ip = 0; ip < 4; ip++) {
        float2 c0 = unpk2(acc[ip][0]), c1 = unpk2(acc[ip][1]);
        float2 c2 = unpk2(acc[ip][2]), c3 = unpk2(acc[ip][3]);
        float4 lo = make_float4(c0.x, c1.x, c2.x, c3.x);
        float4 hi = make_float4(c0.y, c1.y, c2.y, c3.y);
        int r0 = m0 + ty * 8 + 2 * ip;
        *(float4*)&C[(long)r0 * ldc + n0 + tx * 4] = lo;
        *(float4*)&C[(long)(r0 + 1) * ldc + n0 + tx * 4] = hi;
    }
}

// ---------------- es/ed ----------------
__global__ void esed_k(const float* __restrict__ asrc, const float* __restrict__ adst)
{
    int warp = (blockIdx.x * blockDim.x + threadIdx.x) >> 5;
    int lane = threadIdx.x & 31;
    int b = warp >> 13, rem = warp & 8191, h = rem >> 11, n = rem & 2047;
    const float* hr = g_hproj + ((long)(b * Nn + n) * HF + h * Ff);
    float v0 = hr[lane], v1 = hr[lane + 32];
    float s = v0 * asrc[h * Ff + lane] + v1 * asrc[h * Ff + lane + 32];
    float d = v0 * adst[h * Ff + lane] + v1 * adst[h * Ff + lane + 32];
#pragma unroll
    for (int o = 16; o; o >>= 1) {
        s += __shfl_xor_sync(0xffffffffu, s, o);
        d += __shfl_xor_sync(0xffffffffu, d, o);
    }
    if (!lane) { g_es[warp] = s; g_ed[warp] = d; }
}

// ---------------- softmax -> att (bf16 hi/lo) + attention map ----------------
__global__ void __launch_bounds__(256) softmax_att_k(const int* __restrict__ adj,
                                                     int layer, float* __restrict__ omap)
{
    __shared__ float red[8];
    int bi = blockIdx.x;
    int b = bi >> 11, i = bi & 2047;
    int tid = threadIdx.x, lane = tid & 31, wid = tid >> 5;

    const int2* adjrow = (const int2*)(adj + (long)i * Nn);
    float m0r[4], m1r[4], am0[4], am1[4];
#pragma unroll
    for (int k = 0; k < 4; k++) {
        int2 a = adjrow[tid + 256 * k];
        m0r[k] = (a.x > 0) ? 1.f : 0.f;
        m1r[k] = (a.y > 0) ? 1.f : 0.f;
        am0[k] = am1[k] = 0.f;
    }

    for (int hh = 0; hh < Hh; hh++) {
        int ro = ((b << 2) + hh) << 11;
        float esi = g_es[ro + i];
        const float2* edp = (const float2*)(g_ed + ro);

        float p0[4], p1[4];
        float lsum = 0.f;
#pragma unroll
        for (int k = 0; k < 4; k++) {
            float2 ed = edp[tid + 256 * k];
            float s0 = esi + ed.x, s1 = esi + ed.y;
            float e0 = fmaxf(s0, 0.2f * s0), e1 = fmaxf(s1, 0.2f * s1);
            float q0 = __expf(e0) * m0r[k], q1 = __expf(e1) * m1r[k];
            p0[k] = q0; p1[k] = q1;
            lsum += q0 + q1;
        }
#pragma unroll
        for (int o = 16; o; o >>= 1) lsum += __shfl_xor_sync(0xffffffffu, lsum, o);
        if (!lane) red[wid] = lsum;
        __syncthreads();
        float inv = 1.f / (red[0] + red[1] + red[2] + red[3] + red[4] + red[5] + red[6] + red[7]);
        __syncthreads();

        __nv_bfloat162* ah = (__nv_bfloat162*)(g_atth + ((long)(ro + i) << 11));
        __nv_bfloat162* al = (__nv_bfloat162*)(g_attl + ((long)(ro + i) << 11));
#pragma unroll
        for (int k = 0; k < 4; k++) {
            float w0 = p0[k] * inv, w1 = p1[k] * inv;
            __nv_bfloat16 h0 = __float2bfloat16(w0), h1 = __float2bfloat16(w1);
            float l0 = w0 - __bfloat162float(h0), l1 = w1 - __bfloat162float(h1);
            ah[tid + 256 * k] = __halves2bfloat162(h0, h1);
            al[tid + 256 * k] = __halves2bfloat162(__float2bfloat16(l0), __float2bfloat16(l1));
            am0[k] += 0.125f * w0; am1[k] += 0.125f * w1;
        }
    }

    float2* mrow = (float2*)(omap + ((long)bi << 11));
    if (layer == 0) {
#pragma unroll
        for (int k = 0; k < 4; k++) mrow[tid + 256 * k] = make_float2(am0[k], am1[k]);
    } else {
#pragma unroll
        for (int k = 0; k < 4; k++) {
            float2 v = mrow[tid + 256 * k];
            mrow[tid + 256 * k] = make_float2(v.x + am0[k], v.y + am1[k]);
        }
    }
}

// ---------------- transpose hproj -> hT bf16 hi/lo ----------------
__global__ void hT_k() {
    __shared__ float t[32][33];
    int b = blockIdx.z;
    int j0 = blockIdx.x * 32, c0 = blockIdx.y * 32;
    int tx = threadIdx.x, ty = threadIdx.y;
#pragma unroll
    for (int i = 0; i < 4; i++) {
        int j = j0 + ty + 8 * i;
        t[ty + 8 * i][tx] = g_hproj[((long)b * Nn + j) * HF + c0 + tx];
    }
    __syncthreads();
#pragma unroll
    for (int i = 0; i < 4; i++) {
        int c = c0 + ty + 8 * i;
        float v = t[tx][ty + 8 * i];
        __nv_bfloat16 hi = __float2bfloat16(v);
        float lo = v - __bfloat162float(hi);
        long o = ((long)b * HF + c) * Nn + j0 + tx;
        g_hTh[o] = hi;
        g_hTl[o] = __float2bfloat16(lo);
    }
}

// ---------------- wmma att@h GEMM (split-bf16, cp.async double buffer) ----------------
// Per CTA: M=128 rows (i), N=64 (f), K=2048 (j) in 32 chunks of 64. z = b*4+h.
// Stage layout (bytes): Ahi[128x72] 18432 | Alo 18432 | Bhi[64x72] 9216 | Blo 9216
#define A_LDM 72
#define ALO_OFF 18432
#define BHI_OFF 36864
#define BLO_OFF 46080
#define STAGE   55296
#define SM_TOTAL (2 * STAGE)

__device__ __forceinline__ void load_chunk(uint32_t sb, int s, int z, int m0, int c) {
    int tid = threadIdx.x;
    long j0 = (long)c * 64;
    uint32_t base = sb + s * STAGE;
#pragma unroll
    for (int i = 0; i < 4; i++) {
        int q = tid + 256 * i;
        int row = q >> 3, seg = q & 7;
        long go = ((long)z * Nn + m0 + row) * Nn + j0 + seg * 8;
        uint32_t so = base + row * 144 + seg * 16;
        CP16(so, g_atth + go);
        CP16(so + ALO_OFF, g_attl + go);
    }
#pragma unroll
    for (int i = 0; i < 2; i++) {
        int q = tid + 256 * i;
        int row = q >> 3, seg = q & 7;
        long go = ((long)z * 64 + row) * Nn + j0 + seg * 8;
        uint32_t so = base + BHI_OFF + row * 144 + seg * 16;
        CP16(so, g_hTh + go);
        CP16(so + (BLO_OFF - BHI_OFF), g_hTl + go);
    }
    CP_COMMIT();
}

__global__ void __launch_bounds__(256) attmma_k(int layer) {
    extern __shared__ char smem[];
    uint32_t sb = smem_u32(smem);
    int tid = threadIdx.x, wid = tid >> 5;
    int z = blockIdx.z, b = z >> 2, h = z & 3;
    int m0 = blockIdx.x * 128;
    int row0 = wid * 16;

    wmma::fragment<wmma::accumulator, 16, 16, 16, float> acc[4];
#pragma unroll
    for (int n = 0; n < 4; n++) wmma::fill_fragment(acc[n], 0.f);

    load_chunk(sb, 0, z, m0, 0);

    for (int c = 0; c < 32; ++c) {
        if (c + 1 < 32) {
            load_chunk(sb, (c + 1) & 1, z, m0, c + 1);
            CP_WAIT1();
        } else {
            CP_WAIT0();
        }
        __syncthreads();

        const char* st = smem + (c & 1) * STAGE;
        const __nv_bfloat16* Ah = (const __nv_bfloat16*)st;
        const __nv_bfloat16* Al = (const __nv_bfloat16*)(st + ALO_OFF);
        const __nv_bfloat16* Bh = (const __nv_bfloat16*)(st + BHI_OFF);
        const __nv_bfloat16* Bl = (const __nv_bfloat16*)(st + BLO_OFF);

#pragma unroll
        for (int kk = 0; kk < 4; kk++) {
            wmma::fragment<wmma::matrix_a, 16, 16, 16, __nv_bfloat16, wmma::row_major> fa_h, fa_l;
            wmma::load_matrix_sync(fa_h, Ah + row0 * A_LDM + kk * 16, A_LDM);
            wmma::load_matrix_sync(fa_l, Al + row0 * A_LDM + kk * 16, A_LDM);
#pragma unroll
            for (int n = 0; n < 4; n++) {
                wmma::fragment<wmma::matrix_b, 16, 16, 16, __nv_bfloat16, wmma::col_major> fb_h, fb_l;
                wmma::load_matrix_sync(fb_h, Bh + n * 16 * A_LDM + kk * 16, A_LDM);
                wmma::load_matrix_sync(fb_l, Bl + n * 16 * A_LDM + kk * 16, A_LDM);
                wmma::mma_sync(acc[n], fa_h, fb_h, acc[n]);
                wmma::mma_sync(acc[n], fa_h, fb_l, acc[n]);
                wmma::mma_sync(acc[n], fa_l, fb_h, acc[n]);
            }
        }
        __syncthreads();
    }

    // epilogue: accums -> smem -> relu -> global
    float* Cs = (float*)smem;
#pragma unroll
    for (int n = 0; n < 4; n++)
        wmma::store_matrix_sync(Cs + row0 * A_LDM + n * 16, acc[n], A_LDM, wmma::mem_row_major);
    __syncthreads();

    float* C = (layer == 0 ? g_x1 : g_x2) + ((long)(b * Nn + m0) * HF + h * 64);
#pragma unroll
    for (int i = 0; i < 8; i++) {
        int q = tid + 256 * i;           // 2048 float4
        int row = q >> 4, cg = q & 15;
        float4 v = *(float4*)&Cs[row * A_LDM + cg * 4];
        v.x = fmaxf(v.x, 0.f); v.y = fmaxf(v.y, 0.f);
        v.z = fmaxf(v.z, 0.f); v.w = fmaxf(v.w, 0.f);
        *(float4*)(C + (long)row * HF + cg * 4) = v;
    }
}

// ---------------- pools ----------------
__global__ void pool_k(const float* __restrict__ xparam,
                       const float* __restrict__ w, const float* __restrict__ wb,
                       float* __restrict__ out, int mode)
{
    int warp = (blockIdx.x * 256 + threadIdx.x) >> 5;
    int lane = threadIdx.x & 31;
    const float* rows; int rowlen, off; float scale;
    if (mode == 0)      { rows = xparam; rowlen = Dd; off = 0;      scale = 1.f / 128.f; }
    else if (mode == 1) { rows = g_x1;   rowlen = HF; off = Nn;     scale = 1.f; }
    else                { rows = g_x2;   rowlen = HF; off = 2 * Nn; scale = 1.f; }
    const float* rp = rows + (long)warp * rowlen;
    float acc = 0.f;
    if (mode == 0) { for (int c = lane; c < rowlen; c += 32) acc += rp[c]; }
    else           { for (int c = lane; c < rowlen; c += 32) acc += rp[c] * w[c]; }
#pragma unroll
    for (int o = 16; o; o >>= 1) acc += __shfl_xor_sync(0xffffffffu, acc, o);
    if (!lane) {
        int b = warp >> 11, n = warp & 2047;
        out[(long)b * (3 * Nn) + off + n] = acc * scale + (mode == 0 ? 0.f : wb[0]);
    }
}

// ---------------- MLP head ----------------
__global__ void __launch_bounds__(256) fc_part_k(const float* __restrict__ in_param,
                                                 const float* __restrict__ W,
                                                 int use_y1, int IC, int OC)
{
    __shared__ float red0[256], red1[256];
    const float* in = use_y1 ? (const float*)g_y1 : in_param;
    int tid = threadIdx.x;
    int cl = tid & 63, ks = tid >> 6;
    int c = blockIdx.x * 64 + cl;
    int kchunk = IC >> 5;
    int k0 = (blockIdx.y * 4 + ks) * kchunk;
    const float* in0 = in;
    const float* in1 = in + IC;
    float a0 = 0.f, a1 = 0.f;
#pragma unroll 4
    for (int k = k0; k < k0 + kchunk; k++) {
        float w = W[(long)k * OC + c];
        a0 += in0[k] * w;
        a1 += in1[k] * w;
    }
    red0[tid] = a0; red1[tid] = a1;
    __syncthreads();
    if (ks == 0) {
        a0 = red0[tid] + red0[tid + 64] + red0[tid + 128] + red0[tid + 192];
        a1 = red1[tid] + red1[tid + 64] + red1[tid + 128] + red1[tid + 192];
        long base = (long)blockIdx.y * (2 * OC);
        g_part[base + c] = a0;
        g_part[base + OC + c] = a1;
    }
}

__global__ void fc_reduce_k(const float* __restrict__ bias, int mode, int OC, int tot)
{
    int t = blockIdx.x * 256 + threadIdx.x;
    if (t >= tot) return;
    float s = bias[t % OC];
#pragma unroll
    for (int p = 0; p < 8; p++) s += g_part[(long)p * tot + t];
    if (mode == 0) g_fc1[t] = s; else g_fc2[t] = s;
}

__global__ void ln_relu_k(int mode, float* __restrict__ out_param,
                          const float* __restrict__ g, const float* __restrict__ be)
{
    __shared__ float r1[8], r2[8];
    int C = (mode == 0) ? FC1n : FC2n;
    const float* in = (mode == 0) ? (const float*)g_fc1 : (const float*)g_fc2;
    float* outp = (mode == 0) ? (float*)g_y1 : out_param;
    int b = blockIdx.x, tid = threadIdx.x, lane = tid & 31, wid = tid >> 5;
    const float* row = in + (long)b * C;
    float s = 0.f, ss = 0.f;
    for (int c = tid; c < C; c += 256) { float v = row[c]; s += v; ss += v * v; }
#pragma unroll
    for (int o = 16; o; o >>= 1) {
        s  += __shfl_xor_sync(0xffffffffu, s, o);
        ss += __shfl_xor_sync(0xffffffffu, ss, o);
    }
    if (!lane) { r1[wid] = s; r2[wid] = ss; }
    __syncthreads();
    s = 0.f; ss = 0.f;
#pragma unroll
    for (int w = 0; w < 8; w++) { s += r1[w]; ss += r2[w]; }
    float m = s / C;
    float var = ss / C - m * m;
    float r = rsqrtf(var + 1e-5f);
    for (int c = tid; c < C; c += 256) {
        float v = row[c];
        outp[(long)b * C + c] = fmaxf((v - m) * r * g[c] + be[c], 0.f);
    }
}

__global__ void cls_k(const float* __restrict__ feat, const float* __restrict__ W,
                      const float* __restrict__ wb, float* __restrict__ out)
{
    int tid = threadIdx.x;
    if (tid >= 128) return;
    int lane = tid & 31, w = tid >> 5;
    int b = w >> 1, l = w & 1;
    float acc = 0.f;
    for (int k = lane; k < FC2n; k += 32) acc += feat[b * FC2n + k] * W[k * 2 + l];
#pragma unroll
    for (int o = 16; o; o >>= 1) acc += __shfl_xor_sync(0xffffffffu, acc, o);
    if (!lane) out[b * 2 + l] = acc + wb[l];
}

// ---------------- host launcher ----------------
extern "C" void kernel_launch(void* const* d_in, const int* in_sizes, int n_in,
                              void* d_out, int out_size)
{
    const float* x        = (const float*)d_in[0];
    const int*   adj      = (const int*)  d_in[1];
    const float* a1_src   = (const float*)d_in[4];
    const float* a1_dst   = (const float*)d_in[5];
    const float* pool1_W  = (const float*)d_in[6];
    const float* pool1_b  = (const float*)d_in[7];
    const float* a2_src   = (const float*)d_in[9];
    const float* a2_dst   = (const float*)d_in[10];
    const float* pool2_W  = (const float*)d_in[11];
    const float* pool2_b  = (const float*)d_in[12];
    const float* fc1_W    = (const float*)d_in[13];
    const float* fc1_b    = (const float*)d_in[14];
    const float* ln1_g    = (const float*)d_in[15];
    const float* ln1_b    = (const float*)d_in[16];
    const float* fc2_W    = (const float*)d_in[17];
    const float* fc2_b    = (const float*)d_in[18];
    const float* ln2_g    = (const float*)d_in[19];
    const float* ln2_b    = (const float*)d_in[20];
    const float* cls_W    = (const float*)d_in[21];
    const float* cls_b    = (const float*)d_in[22];

    float* out = (float*)d_out;

    cudaFuncSetAttribute(attmma_k, cudaFuncAttributeMaxDynamicSharedMemorySize, SM_TOTAL);

    repack_k<<<256, 256>>>((const float*)d_in[3], (const float*)d_in[8]);

    // layer 1
    gemm_k<<<dim3(32, 4, 1), 256>>>(x, 0);
    esed_k<<<2048, 256>>>(a1_src, a1_dst);
    softmax_att_k<<<4096, 256>>>(adj, 0, out + OUT_MAP);
    hT_k<<<dim3(64, 8, 2), dim3(32, 8)>>>();
    attmma_k<<<dim3(16, 1, 8), 256, SM_TOTAL>>>(0);

    pool_k<<<512, 256>>>(x, pool1_W, pool1_b, out + OUT_GAT, 0);
    pool_k<<<512, 256>>>(x, pool1_W, pool1_b, out + OUT_GAT, 1);

    // layer 2
    gemm_k<<<dim3(32, 4, 1), 256>>>(x, 1);
    esed_k<<<2048, 256>>>(a2_src, a2_dst);
    softmax_att_k<<<4096, 256>>>(adj, 1, out + OUT_MAP);
    hT_k<<<dim3(64, 8, 2), dim3(32, 8)>>>();
    attmma_k<<<dim3(16, 1, 8), 256, SM_TOTAL>>>(1);

    pool_k<<<512, 256>>>(x, pool2_W, pool2_b, out + OUT_GAT, 2);

    // head
    fc_part_k<<<dim3(16, 8), 256>>>(out + OUT_GAT, fc1_W, 0, 3 * Nn, FC1n);
    fc_reduce_k<<<8, 256>>>(fc1_b, 0, FC1n, Bsz * FC1n);
    ln_relu_k<<<2, 256>>>(0, out, ln1_g, ln1_b);

    fc_part_k<<<dim3(4, 8), 256>>>(out, fc2_W, 1, FC1n, FC2n);
    fc_reduce_k<<<2, 256>>>(fc2_b, 1, FC2n, Bsz * FC2n);
    ln_relu_k<<<2, 256>>>(1, out + OUT_FC, ln2_g, ln2_b);

    cls_k<<<1, 128>>>(out + OUT_FC, cls_W, cls_b, out + OUT_LOG);
}